// round 6
// baseline (speedup 1.0000x reference)
#include <cuda_runtime.h>
#include <cstdint>

#define KDIM 256
#define NIT 50
#define C8PITCH 260    // bytes per row (65 words) -> conflict-free rows, cols, and strided gathers

__device__ float g_loss[512];
__device__ unsigned g_cnt = 0;

static constexpr int SMEM_C8_OFF   = 0;        // 256*260 = 66560
static constexpr int SMEM_FSH_OFF  = 66560;    // 1024
static constexpr int SMEM_ECOL_OFF = 67584;    // 1024
static constexpr int SMEM_LUT_OFF  = 68608;    // 1024
static constexpr int SMEM_GSH_OFF  = 69632;    // 1024 (overlaid by sidx/sval after FW)
static constexpr int SMEM_RED_OFF  = 70656;    // 256
static constexpr int SMEM_BYTES    = 70912;    // 69.25 KB -> 3 CTAs/SM

__global__ void __launch_bounds__(256, 3)
cacis_main(const float* __restrict__ scores, const int* __restrict__ targets,
           const float* __restrict__ C, float* __restrict__ out, int B)
{
    extern __shared__ unsigned char smem[];
    unsigned char* c8   = smem + SMEM_C8_OFF;
    float*         fsh  = reinterpret_cast<float*>(smem + SMEM_FSH_OFF);
    float*         ecol = reinterpret_cast<float*>(smem + SMEM_ECOL_OFF);
    float*         lut  = reinterpret_cast<float*>(smem + SMEM_LUT_OFF);
    float*         gsh  = reinterpret_cast<float*>(smem + SMEM_GSH_OFF);
    float*         red  = reinterpret_cast<float*>(smem + SMEM_RED_OFF);
    int*           redi = reinterpret_cast<int*>(red);
    int*           sidx = reinterpret_cast<int*>(gsh);   // overlay, dead after FW grad load
    float*         sval = gsh + 64;
    const float4*  ecol4 = reinterpret_cast<const float4*>(ecol);

    const int t    = threadIdx.x;
    const int lane = t & 31;
    const int warp = t >> 5;
    const int b    = blockIdx.x;
    const float*  __restrict__ Cb  = C + (size_t)b * (KDIM * KDIM);
    const float4* __restrict__ Cb4 = reinterpret_cast<const float4*>(Cb);

    fsh[t] = 0.5f * scores[b * KDIM + t];
    __syncthreads();

    // ---------- PASS 1: stream C once, quantize -> u8 row-major smem, integer sum via dp4a ----------
    // thread t owns float4-column c4 = t&63 of rows 4k + (t>>6); coalesced LDG.128, conflict-free STS.32
    unsigned isum = 0;
    {
        const int c4    = t & 63;
        const int rbase = t >> 6;
#pragma unroll 4
        for (int k = 0; k < 64; k++) {
            float4 v = Cb4[k * 256 + t];
            unsigned q0 = __float2uint_rn(v.x * 255.f);
            unsigned q1 = __float2uint_rn(v.y * 255.f);
            unsigned q2 = __float2uint_rn(v.z * 255.f);
            unsigned q3 = __float2uint_rn(v.w * 255.f);
            unsigned p01 = __byte_perm(q0, q1, 0x0040);
            unsigned p23 = __byte_perm(q2, q3, 0x0040);
            unsigned p   = __byte_perm(p01, p23, 0x5410);
            isum = __dp4a(p, 0x01010101u, isum);
            int row = 4 * k + rbase;
            *reinterpret_cast<unsigned*>(c8 + row * C8PITCH + c4 * 4) = p;
        }
    }
    __syncthreads();

    // diagonal byte (for trace) + reductions: isum, itrace (exact ints), min(f)
    {
        unsigned wdiag = *reinterpret_cast<const unsigned*>(c8 + t * C8PITCH + (t & ~3));
        unsigned itr = (wdiag >> ((t & 3) * 8)) & 255u;
        unsigned ws = __reduce_add_sync(0xffffffffu, isum);
        unsigned wt = __reduce_add_sync(0xffffffffu, itr);
        float fm = fsh[t];
#pragma unroll
        for (int o = 16; o; o >>= 1) fm = fminf(fm, __shfl_xor_sync(0xffffffffu, fm, o));
        if (lane == 0) { red[warp] = fm; redi[8 + warp] = (int)ws; redi[16 + warp] = (int)wt; }
    }
    __syncthreads();
    if (t == 0) {
        int s = 0, tr = 0; float mn = 3.402823466e38f;
#pragma unroll
        for (int w = 0; w < 8; w++) { mn = fminf(mn, red[w]); s += redi[8 + w]; tr += redi[16 + w]; }
        float eps = fmaxf((float)(s - tr) * (1.0f / (255.0f * (KDIM * KDIM - KDIM))), 1e-8f);
        red[24] = eps; red[25] = 1.0f / eps; red[26] = 2.0f * mn;   // minval = lower bound, cancels exactly
    }
    __syncthreads();
    const float eps = red[24], inv_eps = red[25], minval = red[26];

    // exp tables: M~_ij = ecol[i]*ecol[j]*lut[q_ij]  (uniform exp(minval/eps) factor dropped: argmin/alpha-invariant)
    ecol[t] = __expf(-fsh[t] * inv_eps);
    lut[t]  = __expf(-(float)t * (inv_eps * (1.0f / 255.0f)));
    __syncthreads();

    // ---------- PASS 2: rowsum of M~ — thread t owns row t (contiguous, conflict-free) ----------
    {
        const unsigned* rw = reinterpret_cast<const unsigned*>(c8 + t * C8PITCH);
        float s0 = 0.f, s1 = 0.f, s2 = 0.f, s3 = 0.f;
#pragma unroll 8
        for (int c = 0; c < 64; c++) {
            unsigned p = rw[c];
            float4 e4 = ecol4[c];                       // broadcast
            s0 = fmaf(e4.x, lut[p & 255u],         s0);
            s1 = fmaf(e4.y, lut[(p >> 8)  & 255u], s1);
            s2 = fmaf(e4.z, lut[(p >> 16) & 255u], s2);
            s3 = fmaf(e4.w, lut[p >> 24],          s3);
        }
        gsh[t] = ((s0 + s1) + (s2 + s3)) * ecol[t] * (2.0f / KDIM);   // grad_0
    }
    __syncthreads();

    // ---------- Frank-Wolfe (warp 0): lane owns rows lane+32k -> conflict-free LDS.U8 column gather ----------
    if (warp == 0) {
        float g[8], a[8], eci[8];
#pragma unroll
        for (int k = 0; k < 8; k++) {
            int r = lane + 32 * k;
            g[k] = gsh[r]; a[k] = 1.0f / KDIM; eci[k] = ecol[r];
        }
        for (int it = 0; it < NIT; it++) {
            unsigned key = 0xFFFFFFFFu;
#pragma unroll
            for (int k = 0; k < 8; k++)
                key = min(key, (__float_as_uint(g[k]) & 0xFFFFFF00u) | (unsigned)(lane + 32 * k));
            key = __reduce_min_sync(0xffffffffu, key);
            int istar = (int)(key & 0xFFu);

            float gamma = 2.0f / ((float)it + 2.0f);
            float om  = 1.0f - gamma;
            float tge = 2.0f * gamma * ecol[istar];
#pragma unroll
            for (int k = 0; k < 8; k++) {
                int r = lane + 32 * k;
                unsigned q = c8[r * C8PITCH + istar];   // bank = (lane + istar>>2)&31 -> conflict-free
                g[k] = fmaf(tge * eci[k], lut[q], om * g[k]);
                a[k] = om * a[k] + ((r == istar) ? gamma : 0.f);
            }
        }
        // compact support (order-irrelevant for the symmetric pair sum)
        int nS = 0;
#pragma unroll
        for (int k = 0; k < 8; k++) {
            bool nz = (a[k] > 0.f);
            unsigned m = __ballot_sync(0xffffffffu, nz);
            if (nz) {
                int pos = nS + __popc(m & ((1u << lane) - 1u));
                sidx[pos] = lane + 32 * k;
                sval[pos] = a[k];
            }
            nS += __popc(m);
        }
        if (lane == 0) redi[27] = nS;
    }
    __syncthreads();

    // ---------- exact val = alpha^T M alpha (full-precision gmem C), 256 threads ----------
    {
        const int nS  = redi[27];
        const int tot = nS * nS;
        float vp = 0.f;
        for (int p = t; p < tot; p += 256) {
            int pi = p / nS, pj = p - pi * nS;
            int i = sidx[pi], j = sidx[pj];
            float e = (minval - fsh[i] - fsh[j] - Cb[(i << 8) + j]) * inv_eps;   // <= 0
            vp += sval[pi] * sval[pj] * __expf(e);
        }
#pragma unroll
        for (int o = 16; o; o >>= 1) vp += __shfl_xor_sync(0xffffffffu, vp, o);
        if (lane == 0) red[32 + warp] = vp;
    }
    __syncthreads();
    if (warp != 0) return;

    float vtot = (lane < 8) ? red[32 + lane] : 0.f;
#pragma unroll
    for (int o = 4; o; o >>= 1) vtot += __shfl_xor_sync(0xffffffffu, vtot, o);
    vtot = __shfl_sync(0xffffffffu, vtot, 0);

    unsigned prev = 0;
    if (lane == 0) {
        g_loss[b] = minval - eps * logf(vtot) - scores[b * KDIM + targets[b]];
        __threadfence();
        prev = atomicAdd(&g_cnt, 1u);
    }
    prev = __shfl_sync(0xffffffffu, prev, 0);
    if ((int)prev == B - 1) {
        __threadfence();
        float s = 0.f;
        volatile float* gl = g_loss;
        for (int i = lane; i < B; i += 32) s += gl[i];
#pragma unroll
        for (int o = 16; o; o >>= 1) s += __shfl_xor_sync(0xffffffffu, s, o);
        if (lane == 0) { out[0] = s / (float)B; g_cnt = 0; }
    }
}

extern "C" void kernel_launch(void* const* d_in, const int* in_sizes, int n_in,
                              void* d_out, int out_size)
{
    int imin = 0, imax = 0;
    for (int i = 1; i < n_in; i++) {
        if (in_sizes[i] < in_sizes[imin]) imin = i;
        if (in_sizes[i] > in_sizes[imax]) imax = i;
    }
    int imid = 3 - imin - imax;
    const float* scores  = (const float*)d_in[imid];
    const int*   targets = (const int*)d_in[imin];
    const float* C       = (const float*)d_in[imax];
    int B = in_sizes[imin];

    cudaFuncSetAttribute(cacis_main, cudaFuncAttributeMaxDynamicSharedMemorySize, SMEM_BYTES);
    cacis_main<<<B, 256, SMEM_BYTES>>>(scores, targets, C, (float*)d_out, B);
}